// round 16
// baseline (speedup 1.0000x reference)
#include <cuda_runtime.h>
#include <cuda_fp16.h>
#include <math.h>
#include <stdint.h>

// ---------------- problem constants ----------------
#define B_    2
#define S_    2048
#define DIM_  2048
#define H_    16
#define C_    512
#define NOPE_ 128
#define ROPE_ 64
#define V_    128
#define QK_   192
#define BS_   (B_*S_)
#define QLD   3648          // merged [q(3072) | kvpe(576)] row stride

// ---------------- scratch (fp16 pipeline) ----------------
__device__ __half g_qkv[(long long)BS_*QLD];
__device__ __half g_kv [(long long)BS_*C_];
__device__ __half g_kpe[(long long)BS_*ROPE_];
__device__ __half g_knv[(long long)H_*BS_*256];   // per-head [k_nope(128) | v(128)]
__device__ __half g_o2 [(long long)BS_*H_*V_];
__device__ __half g_xh [(long long)BS_*DIM_];
__device__ __half g_wqa[(long long)QLD*DIM_];     // [wq(3072) ; wkv_a(576)] rows
__device__ __half g_wbh[(long long)H_*256*C_];
__device__ __half g_woh[(long long)DIM_*(H_*V_)];

// ---------------- helpers ----------------
__device__ __forceinline__ void mma16(float* c, unsigned a0, unsigned a1, unsigned a2,
                                      unsigned a3, unsigned b0, unsigned b1) {
    asm volatile(
        "mma.sync.aligned.m16n8k16.row.col.f32.f16.f16.f32 "
        "{%0,%1,%2,%3},{%4,%5,%6,%7},{%8,%9},{%0,%1,%2,%3};"
        : "+f"(c[0]), "+f"(c[1]), "+f"(c[2]), "+f"(c[3])
        : "r"(a0), "r"(a1), "r"(a2), "r"(a3), "r"(b0), "r"(b1));
}
__device__ __forceinline__ void ldsm4(unsigned &r0, unsigned &r1, unsigned &r2,
                                      unsigned &r3, uint32_t addr) {
    asm volatile("ldmatrix.sync.aligned.m8n8.x4.shared.b16 {%0,%1,%2,%3}, [%4];"
                 : "=r"(r0), "=r"(r1), "=r"(r2), "=r"(r3) : "r"(addr));
}
__device__ __forceinline__ uint32_t su32(const void* p) {
    uint32_t a;
    asm("{ .reg .u64 t; cvta.to.shared.u64 t, %1; cvt.u32.u64 %0, t; }"
        : "=r"(a) : "l"(p));
    return a;
}
__device__ __forceinline__ unsigned packh2(float a, float b) {
    __half2 h = __floats2half2_rn(a, b);
    return *(unsigned*)&h;
}
__device__ __forceinline__ unsigned packhh(__half a, __half b) {
    __half2 h = __halves2half2(a, b);
    return *(unsigned*)&h;
}

// =====================================================================
// fp32 -> fp16 convert
// =====================================================================
__global__ void hround_k(const float4* __restrict__ src, uint2* __restrict__ dst,
                         int n4)
{
    int i = blockIdx.x * blockDim.x + threadIdx.x;
    if (i < n4) {
        float4 v = src[i];
        uint2 u;
        u.x = packh2(v.x, v.y);
        u.y = packh2(v.z, v.w);
        dst[i] = u;
    }
}

// =====================================================================
// fp16 NT GEMM, m16n8k16 + ldmatrix + 3-stage cp.async.
// 256 threads, 8 warps, warp tile 64x32 -> 2 CTAs/SM.
// =====================================================================
#define HSTG 3
#define HTILE 36864
#define GEMM_SMEM (HSTG*HTILE)

template<int OUTH>
__global__ __launch_bounds__(256, 2) void gemm_h(
    const __half* __restrict__ A, const __half* __restrict__ Bm, void* Cv,
    int M, int N, int K, int lda, int ldb, int ldc,
    long long sAz, long long sBz, long long sCz)
{
    A  += (long long)blockIdx.z * sAz;
    Bm += (long long)blockIdx.z * sBz;
    if (OUTH) Cv = (void*)((__half*)Cv + (long long)blockIdx.z * sCz);
    else      Cv = (void*)((float*)Cv  + (long long)blockIdx.z * sCz);

    extern __shared__ __align__(128) char smem[];
    const uint32_t sbase = su32(smem);

    const int tid  = threadIdx.x;
    const int lane = tid & 31;
    const int warp = tid >> 5;
    const int m0 = blockIdx.y * 128;
    const int n0 = blockIdx.x * 128;
    const int wm = (warp >> 2) * 64;
    const int wn = (warp & 3) * 32;
    const int qr = lane >> 2;
    const int qc = lane & 3;

    const int l15 = lane & 15;
    const int ahl = (lane >> 4) << 3;
    const int bg  = lane >> 3;
    const int brw = ((bg >> 1) << 3) + (lane & 7);
    const int bkl = (bg & 1) << 3;

    float acc[4][4][4];
#pragma unroll
    for (int mi = 0; mi < 4; mi++)
#pragma unroll
        for (int ni = 0; ni < 4; ni++)
#pragma unroll
            for (int j = 0; j < 4; j++) acc[mi][ni][j] = 0.f;

    const int crow = tid >> 3;
    const int cc   = tid & 7;

    auto issue_stage = [&](int buf, int k0) {
        uint32_t abase = sbase + buf * HTILE;
        uint32_t bbase = abase + 18432;
#pragma unroll
        for (int i = 0; i < 4; i++) {
            int row = crow + i * 32;
            uint32_t dst = abase + row * 144 + cc * 16;
            const __half* src = A + (long long)(m0 + row) * lda + k0 + cc * 8;
            asm volatile("cp.async.cg.shared.global [%0], [%1], 16;"
                         :: "r"(dst), "l"(src));
        }
#pragma unroll
        for (int i = 0; i < 4; i++) {
            int row = crow + i * 32;
            uint32_t dst = bbase + row * 144 + cc * 16;
            const __half* src = Bm + (long long)(n0 + row) * ldb + k0 + cc * 8;
            int sz = (n0 + row < N) ? 16 : 0;
            asm volatile("cp.async.cg.shared.global [%0], [%1], 16, %2;"
                         :: "r"(dst), "l"(src), "r"(sz));
        }
        asm volatile("cp.async.commit_group;" ::: "memory");
    };

    const int S = K >> 6;
    issue_stage(0, 0);
    if (S > 1) issue_stage(1, 64);

    for (int s = 0; s < S; s++) {
        if (s + 1 < S) asm volatile("cp.async.wait_group 1;" ::: "memory");
        else           asm volatile("cp.async.wait_group 0;" ::: "memory");
        __syncthreads();
        if (s + 2 < S) issue_stage((s + 2) % HSTG, (s + 2) * 64);

        const uint32_t abase = sbase + (s % HSTG) * HTILE;
        const uint32_t bbase = abase + 18432;

#pragma unroll
        for (int kb = 0; kb < 4; kb++) {
            unsigned a[4][4], b[4][2];
#pragma unroll
            for (int mi = 0; mi < 4; mi++) {
                uint32_t ad = abase + (wm + mi*16 + l15) * 144 + (kb*16 + ahl) * 2;
                ldsm4(a[mi][0], a[mi][1], a[mi][2], a[mi][3], ad);
            }
#pragma unroll
            for (int p = 0; p < 2; p++) {
                uint32_t bd = bbase + (wn + p*16 + brw) * 144 + (kb*16 + bkl) * 2;
                ldsm4(b[2*p][0], b[2*p][1], b[2*p+1][0], b[2*p+1][1], bd);
            }
#pragma unroll
            for (int mi = 0; mi < 4; mi++)
#pragma unroll
                for (int ni = 0; ni < 4; ni++)
                    mma16(acc[mi][ni], a[mi][0], a[mi][1], a[mi][2], a[mi][3],
                          b[ni][0], b[ni][1]);
        }
    }

#pragma unroll
    for (int mi = 0; mi < 4; mi++) {
        int r = m0 + wm + mi * 16 + qr;
#pragma unroll
        for (int ni = 0; ni < 4; ni++) {
            int cn = n0 + wn + ni * 8 + 2 * qc;
            if (cn < N) {
                if (OUTH) {
                    __half* C = (__half*)Cv;
                    *(__half2*)(C + (long long)r * ldc + cn) =
                        __floats2half2_rn(acc[mi][ni][0], acc[mi][ni][1]);
                    *(__half2*)(C + (long long)(r + 8) * ldc + cn) =
                        __floats2half2_rn(acc[mi][ni][2], acc[mi][ni][3]);
                } else {
                    float* C = (float*)Cv;
                    *(float2*)(C + (long long)r * ldc + cn) =
                        make_float2(acc[mi][ni][0], acc[mi][ni][1]);
                    *(float2*)(C + (long long)(r + 8) * ldc + cn) =
                        make_float2(acc[mi][ni][2], acc[mi][ni][3]);
                }
            }
        }
    }
}

// =====================================================================
// RoPE on q_pe inside merged g_qkv. grid = BS_, block = 512
// =====================================================================
__global__ void rope_q_k(__half* __restrict__ q,
                         const float* __restrict__ fcos, const float* __restrict__ fsin)
{
    int bs = blockIdx.x;
    int s  = bs & (S_ - 1);
    int t  = threadIdx.x;
    int h  = t >> 5, i = t & 31;
    float c  = fcos[s*(ROPE_/2) + i];
    float sn = fsin[s*(ROPE_/2) + i];
    __half2* p = (__half2*)(q + (long long)bs * QLD + h*QK_ + NOPE_ + 2*i);
    float2 v = __half22float2(*p);
    *p = __floats2half2_rn(v.x*c - v.y*sn, v.x*sn + v.y*c);
}

// =====================================================================
// RMSNorm(kv)*w and RoPE(k_pe) from merged g_qkv tail. grid = BS_, block = 128
// =====================================================================
__global__ void kv_prep_k(const __half* __restrict__ qkv, const float* __restrict__ w,
                          const float* __restrict__ fcos, const float* __restrict__ fsin,
                          __half* __restrict__ kvout, __half* __restrict__ kpeout)
{
    int bs = blockIdx.x;
    int s  = bs & (S_ - 1);
    const __half* row = qkv + (long long)bs * QLD + 3072;
    __shared__ float red[4];
    int t = threadIdx.x;
    float v[4]; float ss = 0.f;
#pragma unroll
    for (int i = 0; i < 4; i++) {
        v[i] = __half2float(row[t + i*128]);
        ss = fmaf(v[i], v[i], ss);
    }
#pragma unroll
    for (int o = 16; o > 0; o >>= 1) ss += __shfl_xor_sync(0xffffffffu, ss, o);
    if ((t & 31) == 0) red[t >> 5] = ss;
    __syncthreads();
    float tot = red[0] + red[1] + red[2] + red[3];
    float r = rsqrtf(tot * (1.0f/512.0f) + 1e-6f);
#pragma unroll
    for (int i = 0; i < 4; i++) {
        int c = t + i*128;
        kvout[(long long)bs*C_ + c] = __float2half_rn(v[i] * r * w[c]);
    }
    if (t < 32) {
        float c  = fcos[s*(ROPE_/2) + t];
        float sn = fsin[s*(ROPE_/2) + t];
        float2 pe = __half22float2(*(const __half2*)(row + C_ + 2*t));
        *(__half2*)(kpeout + (long long)bs*ROPE_ + 2*t) =
            __floats2half2_rn(pe.x*c - pe.y*sn, pe.x*sn + pe.y*c);
    }
}

// =====================================================================
// fp16 flash attention (m16n8k16 + ldmatrix), single-buffered layout
// trimmed to 113,664B -> 2 CTAs/SM (the occupancy lever).
// CTA: 128 q-rows, 8 warps x 16 rows, K/V tiles of 64.
// =====================================================================
#define FM 128
#define FN 64
#define SK_OFF  (128*400)            // sQ: 128 x 400B = 51200
#define SV_OFF  (SK_OFF + 64*400)    // sK: 64 x 400B  = 25600
#define SP_OFF  (SV_OFF + 128*144)   // sV: 128 x 144B = 18432
#define FLASH_SMEM (SP_OFF + 128*144) // + sP 18432 = 113664 (<= 116224)

__global__ __launch_bounds__(256, 2) void flash_h(
    const __half* __restrict__ q,    // merged g_qkv, row stride QLD
    const __half* __restrict__ knv,  // (H, bs, 256) fp16
    const __half* __restrict__ kpe,  // (bs, 64) fp16
    __half* __restrict__ out)        // (bs, H*128) fp16
{
    extern __shared__ __align__(128) char sm[];
    unsigned* sV = (unsigned*)(sm + SV_OFF);
    unsigned* sP = (unsigned*)(sm + SP_OFF);
    const uint32_t sqb = su32(sm);
    const uint32_t skb = sqb + SK_OFF;
    const uint32_t svb = sqb + SV_OFF;
    const uint32_t spb = sqb + SP_OFF;

    int bx = blockIdx.x;
    int nb = gridDim.x;
    int sblk = (bx & 1) ? (nb - 1 - (bx >> 1)) : (bx >> 1);
    const int s0 = sblk * FM;
    const int h  = blockIdx.y;
    const int b  = blockIdx.z;
    const int tid = threadIdx.x;
    const int lane = tid & 31;
    const int warp = tid >> 5;
    const int rb = warp * 16;
    const int qr = lane >> 2;
    const int qc = lane & 3;
    const int g0 = s0 + rb + qr;
    const int g1 = g0 + 8;

    const int l15 = lane & 15;
    const int ahl = (lane >> 4) << 3;
    const int bg  = lane >> 3;
    const int brw = ((bg >> 1) << 3) + (lane & 7);
    const int bkl = (bg & 1) << 3;

    const __half* knh = knv + (long long)h * BS_ * 256;
    const float SC = 0.07216878364870322f;  // 1/sqrt(192)

    auto loadK = [&](int t0) {
#pragma unroll
        for (int i = 0; i < 6; i++) {
            int id = tid + i * 256;
            int r = id / 24, c = id % 24;
            long long trow = (long long)(b*S_ + t0 + r);
            const __half* src = (c < 16) ? (knh + trow*256 + c*8)
                                         : (kpe + trow*(long long)ROPE_ + (c-16)*8);
            uint32_t dst = skb + (uint32_t)(r*400 + c*16);
            asm volatile("cp.async.cg.shared.global [%0], [%1], 16;"
                         :: "r"(dst), "l"(src));
        }
        asm volatile("cp.async.commit_group;" ::: "memory");
    };

    const int tp = tid & 31;     // t-pair index
    const int dg = tid >> 5;     // d-group (16 d's)
    union HU { uint4 u[2]; __half x[16]; };
    HU vlo, vhi;
    auto ldV = [&](int t0) {
        const __half* base = knh + (long long)(b*S_ + t0 + 2*tp) * 256 + 128 + dg*16;
        vlo.u[0] = *(const uint4*)(base);
        vlo.u[1] = *(const uint4*)(base + 8);
        vhi.u[0] = *(const uint4*)(base + 256);
        vhi.u[1] = *(const uint4*)(base + 264);
    };
    auto stV = [&]() {
#pragma unroll
        for (int d = 0; d < 16; d++)
            sV[(dg*16 + d)*36 + tp] = packhh(vlo.x[d], vhi.x[d]);
    };

    // Q tile (raw uint4 copy)
#pragma unroll
    for (int i = 0; i < 12; i++) {
        int id = tid + i * 256;
        int r = id / 24, c = id % 24;
        *(uint4*)(sm + r*400 + c*16) =
            *(const uint4*)(q + (long long)(b*S_ + s0 + r) * QLD + h*QK_ + c*8);
    }

    float mr0 = -INFINITY, mr1 = -INFINITY, l0 = 0.f, l1 = 0.f;
    float o[16][4];
#pragma unroll
    for (int ni = 0; ni < 16; ni++)
#pragma unroll
        for (int j = 0; j < 4; j++) o[ni][j] = 0.f;

    loadK(0);
    ldV(0);
    asm volatile("cp.async.wait_group 0;" ::: "memory");
    stV();
    __syncthreads();

    const int tlast = s0 + (FM - FN);
    for (int t0 = 0; t0 <= tlast; t0 += FN) {
        const bool domask = (t0 + FN - 1 > s0);
        const bool nxt = (t0 + FN <= tlast);

        // ---- QK (192 = 12 x k16) ----
        float sc[8][4];
#pragma unroll
        for (int ni = 0; ni < 8; ni++)
#pragma unroll
            for (int j = 0; j < 4; j++) sc[ni][j] = 0.f;

#pragma unroll
        for (int kb = 0; kb < 12; kb++) {
            unsigned a0, a1, a2, a3;
            ldsm4(a0, a1, a2, a3,
                  sqb + (rb + l15) * 400 + (kb*16 + ahl) * 2);
            unsigned kb_[8][2];
#pragma unroll
            for (int p = 0; p < 4; p++) {
                ldsm4(kb_[2*p][0], kb_[2*p][1], kb_[2*p+1][0], kb_[2*p+1][1],
                      skb + (p*16 + brw) * 400 + (kb*16 + bkl) * 2);
            }
#pragma unroll
            for (int ni = 0; ni < 8; ni++)
                mma16(sc[ni], a0, a1, a2, a3, kb_[ni][0], kb_[ni][1]);
        }
        __syncthreads();              // done reading sK
        if (nxt) loadK(t0 + FN);      // overlaps softmax + PV

        // ---- softmax (fp32) ----
        float mx0 = -INFINITY, mx1 = -INFINITY;
#pragma unroll
        for (int ni = 0; ni < 8; ni++) {
            float v0 = sc[ni][0]*SC, v1 = sc[ni][1]*SC;
            float v2 = sc[ni][2]*SC, v3 = sc[ni][3]*SC;
            if (domask) {
                int cc = t0 + 8*ni + 2*qc;
                if (cc     > g0) v0 = -1e30f;
                if (cc + 1 > g0) v1 = -1e30f;
                if (cc     > g1) v2 = -1e30f;
                if (cc + 1 > g1) v3 = -1e30f;
            }
            sc[ni][0]=v0; sc[ni][1]=v1; sc[ni][2]=v2; sc[ni][3]=v3;
            mx0 = fmaxf(mx0, fmaxf(v0, v1));
            mx1 = fmaxf(mx1, fmaxf(v2, v3));
        }
        mx0 = fmaxf(mx0, __shfl_xor_sync(0xffffffffu, mx0, 1));
        mx0 = fmaxf(mx0, __shfl_xor_sync(0xffffffffu, mx0, 2));
        mx1 = fmaxf(mx1, __shfl_xor_sync(0xffffffffu, mx1, 1));
        mx1 = fmaxf(mx1, __shfl_xor_sync(0xffffffffu, mx1, 2));

        float mn0 = fmaxf(mr0, mx0), mn1 = fmaxf(mr1, mx1);
        float al0 = __expf(mr0 - mn0), al1 = __expf(mr1 - mn1);

        float s0s = 0.f, s1s = 0.f;
#pragma unroll
        for (int ni = 0; ni < 8; ni++) {
            float p0 = __expf(sc[ni][0] - mn0), p1 = __expf(sc[ni][1] - mn0);
            float p2 = __expf(sc[ni][2] - mn1), p3 = __expf(sc[ni][3] - mn1);
            s0s += p0 + p1; s1s += p2 + p3;
            sP[(rb+qr)*36   + 4*ni + qc] = packh2(p0, p1);
            sP[(rb+qr+8)*36 + 4*ni + qc] = packh2(p2, p3);
        }
        s0s += __shfl_xor_sync(0xffffffffu, s0s, 1);
        s0s += __shfl_xor_sync(0xffffffffu, s0s, 2);
        s1s += __shfl_xor_sync(0xffffffffu, s1s, 1);
        s1s += __shfl_xor_sync(0xffffffffu, s1s, 2);
        l0 = l0 * al0 + s0s;
        l1 = l1 * al1 + s1s;
        mr0 = mn0; mr1 = mn1;

#pragma unroll
        for (int ni = 0; ni < 16; ni++) {
            o[ni][0] *= al0; o[ni][1] *= al0;
            o[ni][2] *= al1; o[ni][3] *= al1;
        }
        __syncwarp();

        if (nxt) ldV(t0 + FN);        // LDG flight overlaps PV

        // ---- PV (64 = 4 x k16) ----
#pragma unroll
        for (int kb = 0; kb < 4; kb++) {
            unsigned a0, a1, a2, a3;
            ldsm4(a0, a1, a2, a3,
                  spb + (rb + l15) * 144 + (kb*16 + ahl) * 2);
            unsigned vb_[16][2];
#pragma unroll
            for (int p = 0; p < 8; p++) {
                ldsm4(vb_[2*p][0], vb_[2*p][1], vb_[2*p+1][0], vb_[2*p+1][1],
                      svb + (p*16 + brw) * 144 + (kb*16 + bkl) * 2);
            }
#pragma unroll
            for (int ni = 0; ni < 16; ni++)
                mma16(o[ni], a0, a1, a2, a3, vb_[ni][0], vb_[ni][1]);
        }
        __syncthreads();              // done reading sV/sP
        if (nxt) {
            stV();
            asm volatile("cp.async.wait_group 0;" ::: "memory");
            __syncthreads();
        }
    }

    float i0 = 1.0f / l0, i1 = 1.0f / l1;
    __half* out0 = out + (long long)(b*S_ + s0 + rb + qr) * (H_*V_) + h*V_;
    __half* out1 = out0 + 8LL * (H_*V_);
#pragma unroll
    for (int ni = 0; ni < 16; ni++) {
        int cn = 8*ni + 2*qc;
        *(__half2*)(out0 + cn) = __floats2half2_rn(o[ni][0]*i0, o[ni][1]*i0);
        *(__half2*)(out1 + cn) = __floats2half2_rn(o[ni][2]*i1, o[ni][3]*i1);
    }
}

// =====================================================================
// Host launch
// =====================================================================
static void* sym_addr(const void* sym) {
    void* p = nullptr;
    cudaGetSymbolAddress(&p, sym);
    return p;
}

extern "C" void kernel_launch(void* const* d_in, const int* in_sizes, int n_in,
                              void* d_out, int out_size)
{
    const float* x     = (const float*)d_in[0];
    const float* wq    = (const float*)d_in[1];
    const float* wkv_a = (const float*)d_in[2];
    const float* wkv_b = (const float*)d_in[3];
    const float* wo    = (const float*)d_in[4];
    const float* kvw   = (const float*)d_in[5];
    const float* fcos  = (const float*)d_in[6];
    const float* fsin  = (const float*)d_in[7];
    float* out = (float*)d_out;

    __half* qkvb = (__half*)sym_addr(g_qkv);
    __half* kvb  = (__half*)sym_addr(g_kv);
    __half* kpeb = (__half*)sym_addr(g_kpe);
    __half* knvb = (__half*)sym_addr(g_knv);
    __half* o2b  = (__half*)sym_addr(g_o2);
    __half* xh   = (__half*)sym_addr(g_xh);
    __half* wqa  = (__half*)sym_addr(g_wqa);
    __half* wbh  = (__half*)sym_addr(g_wbh);
    __half* woh  = (__half*)sym_addr(g_woh);

    static bool attr_done = false;
    if (!attr_done) {
        cudaFuncSetAttribute(gemm_h<1>, cudaFuncAttributeMaxDynamicSharedMemorySize, GEMM_SMEM);
        cudaFuncSetAttribute(gemm_h<0>, cudaFuncAttributeMaxDynamicSharedMemorySize, GEMM_SMEM);
        cudaFuncSetAttribute(flash_h,   cudaFuncAttributeMaxDynamicSharedMemorySize, FLASH_SMEM);
        attr_done = true;
    }

    // 0. convert inputs to fp16
    {
        auto rr = [&](const float* s, __half* d, long long n) {
            int n4 = (int)(n / 4);
            hround_k<<<(n4 + 255) / 256, 256>>>((const float4*)s, (uint2*)d, n4);
        };
        rr(x,     xh,  (long long)BS_*DIM_);
        rr(wq,    wqa, (long long)(H_*QK_)*DIM_);
        rr(wkv_a, wqa + (long long)(H_*QK_)*DIM_, (long long)(C_+ROPE_)*DIM_);
        rr(wkv_b, wbh, (long long)H_*256*C_);
        rr(wo,    woh, (long long)DIM_*(H_*V_));
    }

    dim3 blk(256);

    // 1. merged projections: qkv = xh @ wqa^T   (4096 x 3648, K=2048)
    gemm_h<1><<<dim3(29, 32, 1), blk, GEMM_SMEM>>>(
        xh, wqa, qkvb, BS_, QLD, DIM_, DIM_, DIM_, QLD, 0, 0, 0);

    // 2. rope(q_pe)
    rope_q_k<<<BS_, H_*32>>>(qkvb, fcos, fsin);

    // 3. rmsnorm(kv), rope(k_pe)
    kv_prep_k<<<BS_, 128>>>(qkvb, kvw, fcos, fsin, kvb, kpeb);

    // 4. knv[h] = kv @ wbh[h]^T   (N=256 per head)
    gemm_h<1><<<dim3(2, 32, H_), blk, GEMM_SMEM>>>(
        kvb, wbh, knvb,
        BS_, 256, C_, C_, C_, 256,
        0, (long long)256*C_, (long long)BS_*256);

    // 5. flash attention -> g_o2 (2 CTAs/SM)
    flash_h<<<dim3(S_/FM, H_, B_), dim3(256), FLASH_SMEM>>>(qkvb, knvb, kpeb, o2b);

    // 6. out = o2 @ woh^T   (fp32 out)
    gemm_h<0><<<dim3(16, 32, 1), blk, GEMM_SMEM>>>(
        o2b, woh, out, BS_, DIM_, H_*V_, H_*V_, H_*V_, DIM_, 0, 0, 0);

    (void)in_sizes; (void)n_in; (void)out_size;
}

// round 17
// speedup vs baseline: 1.1161x; 1.1161x over previous
#include <cuda_runtime.h>
#include <cuda_fp16.h>
#include <math.h>
#include <stdint.h>

// ---------------- problem constants ----------------
#define B_    2
#define S_    2048
#define DIM_  2048
#define H_    16
#define C_    512
#define NOPE_ 128
#define ROPE_ 64
#define V_    128
#define QK_   192
#define BS_   (B_*S_)
#define QLD   3648          // merged [q(3072) | kvpe(576)] row stride

// ---------------- scratch (fp16 pipeline) ----------------
__device__ __half g_qkv[(long long)BS_*QLD];
__device__ __half g_kv [(long long)BS_*C_];
__device__ __half g_kpe[(long long)BS_*ROPE_];
__device__ __half g_knv[(long long)H_*BS_*256];   // per-head [k_nope(128) | v(128)]
__device__ __half g_o2 [(long long)BS_*H_*V_];
__device__ __half g_xh [(long long)BS_*DIM_];
__device__ __half g_wqa[(long long)QLD*DIM_];     // [wq(3072) ; wkv_a(576)] rows
__device__ __half g_wbh[(long long)H_*256*C_];
__device__ __half g_woh[(long long)DIM_*(H_*V_)];

// ---------------- helpers ----------------
__device__ __forceinline__ void mma16(float* c, unsigned a0, unsigned a1, unsigned a2,
                                      unsigned a3, unsigned b0, unsigned b1) {
    asm volatile(
        "mma.sync.aligned.m16n8k16.row.col.f32.f16.f16.f32 "
        "{%0,%1,%2,%3},{%4,%5,%6,%7},{%8,%9},{%0,%1,%2,%3};"
        : "+f"(c[0]), "+f"(c[1]), "+f"(c[2]), "+f"(c[3])
        : "r"(a0), "r"(a1), "r"(a2), "r"(a3), "r"(b0), "r"(b1));
}
__device__ __forceinline__ void ldsm4(unsigned &r0, unsigned &r1, unsigned &r2,
                                      unsigned &r3, uint32_t addr) {
    asm volatile("ldmatrix.sync.aligned.m8n8.x4.shared.b16 {%0,%1,%2,%3}, [%4];"
                 : "=r"(r0), "=r"(r1), "=r"(r2), "=r"(r3) : "r"(addr));
}
__device__ __forceinline__ uint32_t su32(const void* p) {
    uint32_t a;
    asm("{ .reg .u64 t; cvta.to.shared.u64 t, %1; cvt.u32.u64 %0, t; }"
        : "=r"(a) : "l"(p));
    return a;
}
__device__ __forceinline__ unsigned packh2(float a, float b) {
    __half2 h = __floats2half2_rn(a, b);
    return *(unsigned*)&h;
}
__device__ __forceinline__ unsigned packhh(__half a, __half b) {
    __half2 h = __halves2half2(a, b);
    return *(unsigned*)&h;
}

// =====================================================================
// fp32 -> fp16 convert
// =====================================================================
__global__ void hround_k(const float4* __restrict__ src, uint2* __restrict__ dst,
                         int n4)
{
    int i = blockIdx.x * blockDim.x + threadIdx.x;
    if (i < n4) {
        float4 v = src[i];
        uint2 u;
        u.x = packh2(v.x, v.y);
        u.y = packh2(v.z, v.w);
        dst[i] = u;
    }
}

// =====================================================================
// fp16 NT GEMM, m16n8k16 + ldmatrix + 3-stage cp.async.
// 256 threads, 8 warps, warp tile 64x32 -> 2 CTAs/SM.
// =====================================================================
#define HSTG 3
#define HTILE 36864
#define GEMM_SMEM (HSTG*HTILE)

template<int OUTH>
__global__ __launch_bounds__(256, 2) void gemm_h(
    const __half* __restrict__ A, const __half* __restrict__ Bm, void* Cv,
    int M, int N, int K, int lda, int ldb, int ldc,
    long long sAz, long long sBz, long long sCz)
{
    A  += (long long)blockIdx.z * sAz;
    Bm += (long long)blockIdx.z * sBz;
    if (OUTH) Cv = (void*)((__half*)Cv + (long long)blockIdx.z * sCz);
    else      Cv = (void*)((float*)Cv  + (long long)blockIdx.z * sCz);

    extern __shared__ __align__(128) char smem[];
    const uint32_t sbase = su32(smem);

    const int tid  = threadIdx.x;
    const int lane = tid & 31;
    const int warp = tid >> 5;
    const int m0 = blockIdx.y * 128;
    const int n0 = blockIdx.x * 128;
    const int wm = (warp >> 2) * 64;
    const int wn = (warp & 3) * 32;
    const int qr = lane >> 2;
    const int qc = lane & 3;

    const int l15 = lane & 15;
    const int ahl = (lane >> 4) << 3;
    const int bg  = lane >> 3;
    const int brw = ((bg >> 1) << 3) + (lane & 7);
    const int bkl = (bg & 1) << 3;

    float acc[4][4][4];
#pragma unroll
    for (int mi = 0; mi < 4; mi++)
#pragma unroll
        for (int ni = 0; ni < 4; ni++)
#pragma unroll
            for (int j = 0; j < 4; j++) acc[mi][ni][j] = 0.f;

    const int crow = tid >> 3;
    const int cc   = tid & 7;

    auto issue_stage = [&](int buf, int k0) {
        uint32_t abase = sbase + buf * HTILE;
        uint32_t bbase = abase + 18432;
#pragma unroll
        for (int i = 0; i < 4; i++) {
            int row = crow + i * 32;
            uint32_t dst = abase + row * 144 + cc * 16;
            const __half* src = A + (long long)(m0 + row) * lda + k0 + cc * 8;
            asm volatile("cp.async.cg.shared.global [%0], [%1], 16;"
                         :: "r"(dst), "l"(src));
        }
#pragma unroll
        for (int i = 0; i < 4; i++) {
            int row = crow + i * 32;
            uint32_t dst = bbase + row * 144 + cc * 16;
            const __half* src = Bm + (long long)(n0 + row) * ldb + k0 + cc * 8;
            int sz = (n0 + row < N) ? 16 : 0;
            asm volatile("cp.async.cg.shared.global [%0], [%1], 16, %2;"
                         :: "r"(dst), "l"(src), "r"(sz));
        }
        asm volatile("cp.async.commit_group;" ::: "memory");
    };

    const int S = K >> 6;
    issue_stage(0, 0);
    if (S > 1) issue_stage(1, 64);

    for (int s = 0; s < S; s++) {
        if (s + 1 < S) asm volatile("cp.async.wait_group 1;" ::: "memory");
        else           asm volatile("cp.async.wait_group 0;" ::: "memory");
        __syncthreads();
        if (s + 2 < S) issue_stage((s + 2) % HSTG, (s + 2) * 64);

        const uint32_t abase = sbase + (s % HSTG) * HTILE;
        const uint32_t bbase = abase + 18432;

#pragma unroll
        for (int kb = 0; kb < 4; kb++) {
            unsigned a[4][4], b[4][2];
#pragma unroll
            for (int mi = 0; mi < 4; mi++) {
                uint32_t ad = abase + (wm + mi*16 + l15) * 144 + (kb*16 + ahl) * 2;
                ldsm4(a[mi][0], a[mi][1], a[mi][2], a[mi][3], ad);
            }
#pragma unroll
            for (int p = 0; p < 2; p++) {
                uint32_t bd = bbase + (wn + p*16 + brw) * 144 + (kb*16 + bkl) * 2;
                ldsm4(b[2*p][0], b[2*p][1], b[2*p+1][0], b[2*p+1][1], bd);
            }
#pragma unroll
            for (int mi = 0; mi < 4; mi++)
#pragma unroll
                for (int ni = 0; ni < 4; ni++)
                    mma16(acc[mi][ni], a[mi][0], a[mi][1], a[mi][2], a[mi][3],
                          b[ni][0], b[ni][1]);
        }
    }

#pragma unroll
    for (int mi = 0; mi < 4; mi++) {
        int r = m0 + wm + mi * 16 + qr;
#pragma unroll
        for (int ni = 0; ni < 4; ni++) {
            int cn = n0 + wn + ni * 8 + 2 * qc;
            if (cn < N) {
                if (OUTH) {
                    __half* C = (__half*)Cv;
                    *(__half2*)(C + (long long)r * ldc + cn) =
                        __floats2half2_rn(acc[mi][ni][0], acc[mi][ni][1]);
                    *(__half2*)(C + (long long)(r + 8) * ldc + cn) =
                        __floats2half2_rn(acc[mi][ni][2], acc[mi][ni][3]);
                } else {
                    float* C = (float*)Cv;
                    *(float2*)(C + (long long)r * ldc + cn) =
                        make_float2(acc[mi][ni][0], acc[mi][ni][1]);
                    *(float2*)(C + (long long)(r + 8) * ldc + cn) =
                        make_float2(acc[mi][ni][2], acc[mi][ni][3]);
                }
            }
        }
    }
}

// =====================================================================
// RoPE on q_pe inside merged g_qkv. grid = BS_, block = 512
// =====================================================================
__global__ void rope_q_k(__half* __restrict__ q,
                         const float* __restrict__ fcos, const float* __restrict__ fsin)
{
    int bs = blockIdx.x;
    int s  = bs & (S_ - 1);
    int t  = threadIdx.x;
    int h  = t >> 5, i = t & 31;
    float c  = fcos[s*(ROPE_/2) + i];
    float sn = fsin[s*(ROPE_/2) + i];
    __half2* p = (__half2*)(q + (long long)bs * QLD + h*QK_ + NOPE_ + 2*i);
    float2 v = __half22float2(*p);
    *p = __floats2half2_rn(v.x*c - v.y*sn, v.x*sn + v.y*c);
}

// =====================================================================
// RMSNorm(kv)*w and RoPE(k_pe) from merged g_qkv tail. grid = BS_, block = 128
// =====================================================================
__global__ void kv_prep_k(const __half* __restrict__ qkv, const float* __restrict__ w,
                          const float* __restrict__ fcos, const float* __restrict__ fsin,
                          __half* __restrict__ kvout, __half* __restrict__ kpeout)
{
    int bs = blockIdx.x;
    int s  = bs & (S_ - 1);
    const __half* row = qkv + (long long)bs * QLD + 3072;
    __shared__ float red[4];
    int t = threadIdx.x;
    float v[4]; float ss = 0.f;
#pragma unroll
    for (int i = 0; i < 4; i++) {
        v[i] = __half2float(row[t + i*128]);
        ss = fmaf(v[i], v[i], ss);
    }
#pragma unroll
    for (int o = 16; o > 0; o >>= 1) ss += __shfl_xor_sync(0xffffffffu, ss, o);
    if ((t & 31) == 0) red[t >> 5] = ss;
    __syncthreads();
    float tot = red[0] + red[1] + red[2] + red[3];
    float r = rsqrtf(tot * (1.0f/512.0f) + 1e-6f);
#pragma unroll
    for (int i = 0; i < 4; i++) {
        int c = t + i*128;
        kvout[(long long)bs*C_ + c] = __float2half_rn(v[i] * r * w[c]);
    }
    if (t < 32) {
        float c  = fcos[s*(ROPE_/2) + t];
        float sn = fsin[s*(ROPE_/2) + t];
        float2 pe = __half22float2(*(const __half2*)(row + C_ + 2*t));
        *(__half2*)(kpeout + (long long)bs*ROPE_ + 2*t) =
            __floats2half2_rn(pe.x*c - pe.y*sn, pe.x*sn + pe.y*c);
    }
}

// =====================================================================
// fp16 flash attention: R13 double-buffered K/V (1 barrier/iter,
// 1 CTA/SM) + Q FRAGMENTS HOISTED INTO REGISTERS (qf[12][4]).
// CTA: 128 q-rows, 8 warps x 16 rows, K/V tiles of 64. ~154KB smem.
// =====================================================================
#define FM 128
#define FN 64
#define SQ_SZ  (128*400)
#define SK_SZ  (64*400)
#define SV_SZ  (128*144)
#define SK0_OFF SQ_SZ
#define SV0_OFF (SK0_OFF + 2*SK_SZ)
#define SP_OFF2 (SV0_OFF + 2*SV_SZ)
#define FLASH_SMEM (SP_OFF2 + SV_SZ)   // 157696

__global__ __launch_bounds__(256, 1) void flash_h(
    const __half* __restrict__ q,    // merged g_qkv, row stride QLD
    const __half* __restrict__ knv,  // (H, bs, 256) fp16
    const __half* __restrict__ kpe,  // (bs, 64) fp16
    __half* __restrict__ out)        // (bs, H*128) fp16
{
    extern __shared__ __align__(128) char sm[];
    const uint32_t sqb = su32(sm);
    const uint32_t spb = sqb + SP_OFF2;
    unsigned* sP = (unsigned*)(sm + SP_OFF2);

    int bx = blockIdx.x;
    int nb = gridDim.x;
    int sblk = (bx & 1) ? (nb - 1 - (bx >> 1)) : (bx >> 1);
    const int s0 = sblk * FM;
    const int h  = blockIdx.y;
    const int b  = blockIdx.z;
    const int tid = threadIdx.x;
    const int lane = tid & 31;
    const int warp = tid >> 5;
    const int rb = warp * 16;
    const int qr = lane >> 2;
    const int qc = lane & 3;
    const int g0 = s0 + rb + qr;
    const int g1 = g0 + 8;

    const int l15 = lane & 15;
    const int ahl = (lane >> 4) << 3;
    const int bg  = lane >> 3;
    const int brw = ((bg >> 1) << 3) + (lane & 7);
    const int bkl = (bg & 1) << 3;

    const __half* knh = knv + (long long)h * BS_ * 256;
    const float SC = 0.07216878364870322f;  // 1/sqrt(192)

    auto loadK = [&](int t0, int buf) {
        const uint32_t kb0 = sqb + SK0_OFF + buf * SK_SZ;
#pragma unroll
        for (int i = 0; i < 6; i++) {
            int id = tid + i * 256;
            int r = id / 24, c = id % 24;
            long long trow = (long long)(b*S_ + t0 + r);
            const __half* src = (c < 16) ? (knh + trow*256 + c*8)
                                         : (kpe + trow*(long long)ROPE_ + (c-16)*8);
            uint32_t dst = kb0 + (uint32_t)(r*400 + c*16);
            asm volatile("cp.async.cg.shared.global [%0], [%1], 16;"
                         :: "r"(dst), "l"(src));
        }
        asm volatile("cp.async.commit_group;" ::: "memory");
    };

    const int tp = tid & 31;     // t-pair index
    const int dg = tid >> 5;     // d-group (16 d's)
    union HU { uint4 u[2]; __half x[16]; };
    HU vlo, vhi;
    auto ldV = [&](int t0) {
        const __half* base = knh + (long long)(b*S_ + t0 + 2*tp) * 256 + 128 + dg*16;
        vlo.u[0] = *(const uint4*)(base);
        vlo.u[1] = *(const uint4*)(base + 8);
        vhi.u[0] = *(const uint4*)(base + 256);
        vhi.u[1] = *(const uint4*)(base + 264);
    };
    auto stV = [&](int buf) {
        unsigned* sV = (unsigned*)(sm + SV0_OFF + buf * SV_SZ);
#pragma unroll
        for (int d = 0; d < 16; d++)
            sV[(dg*16 + d)*36 + tp] = packhh(vlo.x[d], vhi.x[d]);
    };

    // Q tile (raw uint4 copy)
#pragma unroll
    for (int i = 0; i < 12; i++) {
        int id = tid + i * 256;
        int r = id / 24, c = id % 24;
        *(uint4*)(sm + r*400 + c*16) =
            *(const uint4*)(q + (long long)(b*S_ + s0 + r) * QLD + h*QK_ + c*8);
    }

    float mr0 = -INFINITY, mr1 = -INFINITY, l0 = 0.f, l1 = 0.f;
    float o[16][4];
#pragma unroll
    for (int ni = 0; ni < 16; ni++)
#pragma unroll
        for (int j = 0; j < 4; j++) o[ni][j] = 0.f;

    loadK(0, 0);
    ldV(0);
    asm volatile("cp.async.wait_group 0;" ::: "memory");
    stV(0);
    __syncthreads();

    // ---- hoist Q fragments into registers (loop-invariant) ----
    unsigned qf[12][4];
#pragma unroll
    for (int kb = 0; kb < 12; kb++)
        ldsm4(qf[kb][0], qf[kb][1], qf[kb][2], qf[kb][3],
              sqb + (rb + l15) * 400 + (kb*16 + ahl) * 2);

    const int tlast = s0 + (FM - FN);
    int cur = 0;
    for (int t0 = 0; t0 <= tlast; t0 += FN, cur ^= 1) {
        const bool domask = (t0 + FN - 1 > s0);
        const bool nxt = (t0 + FN <= tlast);
        const uint32_t skb = sqb + SK0_OFF + cur * SK_SZ;
        const uint32_t svb = sqb + SV0_OFF + cur * SV_SZ;

        // ---- QK (192 = 12 x k16), A from registers ----
        float sc[8][4];
#pragma unroll
        for (int ni = 0; ni < 8; ni++)
#pragma unroll
            for (int j = 0; j < 4; j++) sc[ni][j] = 0.f;

#pragma unroll
        for (int kb = 0; kb < 12; kb++) {
            unsigned kb_[8][2];
#pragma unroll
            for (int p = 0; p < 4; p++) {
                ldsm4(kb_[2*p][0], kb_[2*p][1], kb_[2*p+1][0], kb_[2*p+1][1],
                      skb + (p*16 + brw) * 400 + (kb*16 + bkl) * 2);
            }
#pragma unroll
            for (int ni = 0; ni < 8; ni++)
                mma16(sc[ni], qf[kb][0], qf[kb][1], qf[kb][2], qf[kb][3],
                      kb_[ni][0], kb_[ni][1]);
        }
        // issue next K into the OTHER buffer (WAR cleared by last iter's barrier)
        if (nxt) loadK(t0 + FN, cur ^ 1);

        // ---- softmax (fp32) ----
        float mx0 = -INFINITY, mx1 = -INFINITY;
#pragma unroll
        for (int ni = 0; ni < 8; ni++) {
            float v0 = sc[ni][0]*SC, v1 = sc[ni][1]*SC;
            float v2 = sc[ni][2]*SC, v3 = sc[ni][3]*SC;
            if (domask) {
                int cc = t0 + 8*ni + 2*qc;
                if (cc     > g0) v0 = -1e30f;
                if (cc + 1 > g0) v1 = -1e30f;
                if (cc     > g1) v2 = -1e30f;
                if (cc + 1 > g1) v3 = -1e30f;
            }
            sc[ni][0]=v0; sc[ni][1]=v1; sc[ni][2]=v2; sc[ni][3]=v3;
            mx0 = fmaxf(mx0, fmaxf(v0, v1));
            mx1 = fmaxf(mx1, fmaxf(v2, v3));
        }
        mx0 = fmaxf(mx0, __shfl_xor_sync(0xffffffffu, mx0, 1));
        mx0 = fmaxf(mx0, __shfl_xor_sync(0xffffffffu, mx0, 2));
        mx1 = fmaxf(mx1, __shfl_xor_sync(0xffffffffu, mx1, 1));
        mx1 = fmaxf(mx1, __shfl_xor_sync(0xffffffffu, mx1, 2));

        float mn0 = fmaxf(mr0, mx0), mn1 = fmaxf(mr1, mx1);
        float al0 = __expf(mr0 - mn0), al1 = __expf(mr1 - mn1);

        float s0s = 0.f, s1s = 0.f;
#pragma unroll
        for (int ni = 0; ni < 8; ni++) {
            float p0 = __expf(sc[ni][0] - mn0), p1 = __expf(sc[ni][1] - mn0);
            float p2 = __expf(sc[ni][2] - mn1), p3 = __expf(sc[ni][3] - mn1);
            s0s += p0 + p1; s1s += p2 + p3;
            sP[(rb+qr)*36   + 4*ni + qc] = packh2(p0, p1);
            sP[(rb+qr+8)*36 + 4*ni + qc] = packh2(p2, p3);
        }
        s0s += __shfl_xor_sync(0xffffffffu, s0s, 1);
        s0s += __shfl_xor_sync(0xffffffffu, s0s, 2);
        s1s += __shfl_xor_sync(0xffffffffu, s1s, 1);
        s1s += __shfl_xor_sync(0xffffffffu, s1s, 2);
        l0 = l0 * al0 + s0s;
        l1 = l1 * al1 + s1s;
        mr0 = mn0; mr1 = mn1;

#pragma unroll
        for (int ni = 0; ni < 16; ni++) {
            o[ni][0] *= al0; o[ni][1] *= al0;
            o[ni][2] *= al1; o[ni][3] *= al1;
        }
        __syncwarp();                 // P rows are warp-private

        if (nxt) ldV(t0 + FN);        // LDG flight overlaps PV

        // ---- PV (64 = 4 x k16) ----
#pragma unroll
        for (int kb = 0; kb < 4; kb++) {
            unsigned a0, a1, a2, a3;
            ldsm4(a0, a1, a2, a3,
                  spb + (rb + l15) * 144 + (kb*16 + ahl) * 2);
            unsigned vb_[16][2];
#pragma unroll
            for (int p = 0; p < 8; p++) {
                ldsm4(vb_[2*p][0], vb_[2*p][1], vb_[2*p+1][0], vb_[2*p+1][1],
                      svb + (p*16 + brw) * 144 + (kb*16 + bkl) * 2);
            }
#pragma unroll
            for (int ni = 0; ni < 16; ni++)
                mma16(o[ni], a0, a1, a2, a3, vb_[ni][0], vb_[ni][1]);
        }

        if (nxt) {
            stV(cur ^ 1);             // other V buffer (WAR cleared last iter)
            asm volatile("cp.async.wait_group 0;" ::: "memory");
            __syncthreads();          // single barrier: publish K + V
        }
    }

    float i0 = 1.0f / l0, i1 = 1.0f / l1;
    __half* out0 = out + (long long)(b*S_ + s0 + rb + qr) * (H_*V_) + h*V_;
    __half* out1 = out0 + 8LL * (H_*V_);
#pragma unroll
    for (int ni = 0; ni < 16; ni++) {
        int cn = 8*ni + 2*qc;
        *(__half2*)(out0 + cn) = __floats2half2_rn(o[ni][0]*i0, o[ni][1]*i0);
        *(__half2*)(out1 + cn) = __floats2half2_rn(o[ni][2]*i1, o[ni][3]*i1);
    }
}

// =====================================================================
// Host launch
// =====================================================================
static void* sym_addr(const void* sym) {
    void* p = nullptr;
    cudaGetSymbolAddress(&p, sym);
    return p;
}

extern "C" void kernel_launch(void* const* d_in, const int* in_sizes, int n_in,
                              void* d_out, int out_size)
{
    const float* x     = (const float*)d_in[0];
    const float* wq    = (const float*)d_in[1];
    const float* wkv_a = (const float*)d_in[2];
    const float* wkv_b = (const float*)d_in[3];
    const float* wo    = (const float*)d_in[4];
    const float* kvw   = (const float*)d_in[5];
    const float* fcos  = (const float*)d_in[6];
    const float* fsin  = (const float*)d_in[7];
    float* out = (float*)d_out;

    __half* qkvb = (__half*)sym_addr(g_qkv);
    __half* kvb  = (__half*)sym_addr(g_kv);
    __half* kpeb = (__half*)sym_addr(g_kpe);
    __half* knvb = (__half*)sym_addr(g_knv);
    __half* o2b  = (__half*)sym_addr(g_o2);
    __half* xh   = (__half*)sym_addr(g_xh);
    __half* wqa  = (__half*)sym_addr(g_wqa);
    __half* wbh  = (__half*)sym_addr(g_wbh);
    __half* woh  = (__half*)sym_addr(g_woh);

    static bool attr_done = false;
    if (!attr_done) {
        cudaFuncSetAttribute(gemm_h<1>, cudaFuncAttributeMaxDynamicSharedMemorySize, GEMM_SMEM);
        cudaFuncSetAttribute(gemm_h<0>, cudaFuncAttributeMaxDynamicSharedMemorySize, GEMM_SMEM);
        cudaFuncSetAttribute(flash_h,   cudaFuncAttributeMaxDynamicSharedMemorySize, FLASH_SMEM);
        attr_done = true;
    }

    // 0. convert inputs to fp16
    {
        auto rr = [&](const float* s, __half* d, long long n) {
            int n4 = (int)(n / 4);
            hround_k<<<(n4 + 255) / 256, 256>>>((const float4*)s, (uint2*)d, n4);
        };
        rr(x,     xh,  (long long)BS_*DIM_);
        rr(wq,    wqa, (long long)(H_*QK_)*DIM_);
        rr(wkv_a, wqa + (long long)(H_*QK_)*DIM_, (long long)(C_+ROPE_)*DIM_);
        rr(wkv_b, wbh, (long long)H_*256*C_);
        rr(wo,    woh, (long long)DIM_*(H_*V_));
    }

    dim3 blk(256);

    // 1. merged projections: qkv = xh @ wqa^T   (4096 x 3648, K=2048)
    gemm_h<1><<<dim3(29, 32, 1), blk, GEMM_SMEM>>>(
        xh, wqa, qkvb, BS_, QLD, DIM_, DIM_, DIM_, QLD, 0, 0, 0);

    // 2. rope(q_pe)
    rope_q_k<<<BS_, H_*32>>>(qkvb, fcos, fsin);

    // 3. rmsnorm(kv), rope(k_pe)
    kv_prep_k<<<BS_, 128>>>(qkvb, kvw, fcos, fsin, kvb, kpeb);

    // 4. knv[h] = kv @ wbh[h]^T   (N=256 per head)
    gemm_h<1><<<dim3(2, 32, H_), blk, GEMM_SMEM>>>(
        kvb, wbh, knvb,
        BS_, 256, C_, C_, C_, 256,
        0, (long long)256*C_, (long long)BS_*256);

    // 5. flash attention -> g_o2
    flash_h<<<dim3(S_/FM, H_, B_), dim3(256), FLASH_SMEM>>>(qkvb, knvb, kpeb, o2b);

    // 6. out = o2 @ woh^T   (fp32 out)
    gemm_h<0><<<dim3(16, 32, 1), blk, GEMM_SMEM>>>(
        o2b, woh, out, BS_, DIM_, H_*V_, H_*V_, H_*V_, DIM_, 0, 0, 0);

    (void)in_sizes; (void)n_in; (void)out_size;
}